// round 16
// baseline (speedup 1.0000x reference)
#include <cuda_runtime.h>
#include <cuda_fp16.h>
#include <mma.h>
#include <cstdint>
#include <cstddef>

using namespace nvcuda;

// ============================================================================
// Problem: hidden [B,2048] f32, labels [B,28] i64/i32, W [280,2048] f32,
// bias [280] f32.  logits = hidden @ W^T + bias;  loss = mean NLL / 28.
// fp16 HMMA lane, BK=64 (32 chunks). Split-depth rings: A-raw ring of 2
// (consumed by same-thread convert -> no barrier needed for overwrite),
// B fp16 ring of 3 (consumed by MMAs, barrier-protected). ONE __syncthreads
// per chunk. Convert runs after MMAs (hides under tensor drain).
// ============================================================================
static constexpr int KDIM = 2048;
static constexpr int BATCH_MAX = 32768;
static constexpr int NTOT = 280;
static constexpr int NPAD = 288;        // 18 * 16
static constexpr int BM   = 128;
static constexpr int BK   = 64;         // K per chunk
static constexpr int NCH  = KDIM / BK;  // 32
static constexpr int THREADS = 384;     // 12 warps: 2 (m) x 6 (n)

static constexpr int LDH = 64;          // fp16 row stride (halves) for ah/B
static constexpr int LDC = 292;         // f32 C rows

// SMEM layout (bytes)
static constexpr int SM_BIAS = 0;                         // 288 f32 (1152B)
static constexpr int SM_A    = 1280;                      // A raw ring x2
static constexpr int A_SZ    = BM * 256;                  // 32768 (64 f32/row)
static constexpr int SM_B    = SM_A + 2 * A_SZ;           // 66816, B ring x3
static constexpr int B_SZ    = NPAD * 128;                // 36864 (64 halves)
static constexpr int SM_AH   = SM_B + 3 * B_SZ;           // 177408, ah x2
static constexpr int AH_SZ   = BM * 128;                  // 16384
static constexpr int SM_END  = SM_AH + 2 * AH_SZ;         // 210176
static constexpr int SM_C    = SM_A;                      // epilogue reuse
static constexpr int SM_EPI  = SM_A + BM * LDC * 4;       // 150784
static constexpr int SM_TOTAL = (SM_END > SM_EPI) ? SM_END : SM_EPI;

__device__ __forceinline__ uint32_t smem_u32(const void* p) {
    uint32_t a;
    asm("{ .reg .u64 t; cvta.to.shared.u64 t, %1; cvt.u32.u64 %0, t; }"
        : "=r"(a) : "l"(p));
    return a;
}

#define CP_ASYNC16(dst, src) \
    asm volatile("cp.async.cg.shared.global [%0], [%1], 16;" \
                 :: "r"(dst), "l"(src))
#define CP_COMMIT() asm volatile("cp.async.commit_group;" ::: "memory")
#define CP_WAIT(n)  asm volatile("cp.async.wait_group %0;" :: "n"(n) : "memory")

// ============================================================================
// Device scratch
// ============================================================================
__device__ __align__(16) __half g_whalf[NPAD * KDIM];   // fp16 W, zero-padded
__device__ float  g_logits_scratch[(size_t)BATCH_MAX * NTOT];
__device__ float  g_loss_scratch[1];
__device__ int    g_lab64;

// ============================================================================
// Prep: W -> g_whalf (fp16 RN, rows >= 280 zero). Label dtype detect.
// ============================================================================
__global__ void prep_w_kernel(const float* __restrict__ W,
                              const int* __restrict__ lab) {
    int idx = blockIdx.x * blockDim.x + threadIdx.x;
    if (idx < NPAD * KDIM) {
        int r = idx >> 11;   // / 2048
        g_whalf[idx] = (r < NTOT) ? __float2half_rn(W[idx]) : __half(0.f);
    }
    if (idx == 0) {
        int odd_or = 0;
        #pragma unroll 8
        for (int i = 0; i < 64; i++) odd_or |= lab[2 * i + 1];
        g_lab64 = (odd_or == 0) ? 1 : 0;
    }
}

// ============================================================================
// Fused GEMM (fp16 wmma m16n16k16, BK=64) + bias + logits + loss
// Loop: sync -> MMA(kc) -> issue(kc+2) -> commit -> wait(1) -> convert(kc+1).
// ============================================================================
__global__ void __launch_bounds__(THREADS, 1)
gemm_loss_kernel(const float* __restrict__ hidden,
                 const float* __restrict__ bias,
                 const int*   __restrict__ lab,
                 float* __restrict__ logits_arg,
                 float* __restrict__ loss_out,
                 int batch)
{
    extern __shared__ char smem[];
    float* sbias = reinterpret_cast<float*>(smem + SM_BIAS);
    float* logits = logits_arg ? logits_arg : g_logits_scratch;

    const uint32_t sbase = smem_u32(smem);
    const int tid = threadIdx.x;
    const int wid = tid >> 5;
    const int wm  = wid / 6;     // 0..1 -> 64-row slice
    const int wn  = wid % 6;     // 0..5 -> 48-col slice
    const int m0  = blockIdx.x * BM;

    for (int i = tid; i < NPAD; i += THREADS)
        sbias[i] = (i < NTOT) ? bias[i] : 0.f;

    wmma::fragment<wmma::accumulator, 16, 16, 16, float> c[4][3];
    #pragma unroll
    for (int i = 0; i < 4; i++)
        #pragma unroll
        for (int j = 0; j < 3; j++)
            wmma::fill_fragment(c[i][j], 0.f);

    // ---- cp.async: A raw f32 128x64 (2048 x 16B), B fp16 288x64 (2304 x 16B)
    auto issue_stage = [&](int kc2, int ab, int bb) {
        const uint32_t a_dst = sbase + SM_A + ab * A_SZ;
        const uint32_t b_dst = sbase + SM_B + bb * B_SZ;
        const int k0 = kc2 * BK;
        #pragma unroll
        for (int i = 0; i < 6; i++) {
            int idx = tid + i * THREADS;
            if (idx < 2048) {
                int r = idx >> 4, v = idx & 15;
                const float* src = hidden + (size_t)(m0 + r) * KDIM + k0 + v * 4;
                CP_ASYNC16(a_dst + (uint32_t)(r * 256 + v * 16), src);
            }
        }
        #pragma unroll
        for (int i = 0; i < 6; i++) {
            int idx = tid + i * THREADS;
            int r = idx >> 3, v = idx & 7;
            const __half* src = g_whalf + (size_t)r * KDIM + k0 + v * 8;
            CP_ASYNC16(b_dst + (uint32_t)(r * 128 + v * 16), src);
        }
    };

    // Convert THIS thread's own A pieces of abuf `ab` -> fp16 dst_ah.
    // Own cp.async data is visible after wait_group (no barrier needed).
    auto convert_a = [&](int ab, __half* dst_ah) {
        const char* stg = smem + SM_A + ab * A_SZ;
        #pragma unroll
        for (int i = 0; i < 6; i++) {
            int idx = tid + i * THREADS;
            if (idx < 2048) {
                int r = idx >> 4, v = idx & 15;
                float4 f = *reinterpret_cast<const float4*>(stg + r * 256 + v * 16);
                __half2 h0 = __floats2half2_rn(f.x, f.y);
                __half2 h1 = __floats2half2_rn(f.z, f.w);
                uint2 u = make_uint2(*reinterpret_cast<uint32_t*>(&h0),
                                     *reinterpret_cast<uint32_t*>(&h1));
                *reinterpret_cast<uint2*>(dst_ah + r * LDH + v * 4) = u;
            }
        }
    };

    __half* ah0 = reinterpret_cast<__half*>(smem + SM_AH);
    __half* ah1 = reinterpret_cast<__half*>(smem + SM_AH + AH_SZ);

    // prologue: chunks 0,1 in flight; convert chunk 0 (own pieces)
    issue_stage(0, 0, 0); CP_COMMIT();
    issue_stage(1, 1, 1); CP_COMMIT();
    CP_WAIT(1);                 // own chunk-0 copies complete
    convert_a(0, ah0);

    for (int kc = 0; kc < NCH; kc++) {
        __syncthreads();        // publishes bbuf[kc%3] (all threads' B copies)
                                // and ah[kc&1]; frees bbuf[(kc-1)%3] + ah other

        // MMA chunk kc: A from ah[kc&1], B from bbuf[kc%3]
        const __half* ah = (kc & 1) ? ah1 : ah0;
        const __half* Bs = reinterpret_cast<const __half*>(
            smem + SM_B + (kc % 3) * B_SZ);

        #pragma unroll
        for (int ks = 0; ks < 4; ks++) {
            const int k0 = ks * 16;
            wmma::fragment<wmma::matrix_a, 16, 16, 16, __half,
                           wmma::row_major> a[4];
            wmma::fragment<wmma::matrix_b, 16, 16, 16, __half,
                           wmma::col_major> b[3];
            #pragma unroll
            for (int i = 0; i < 4; i++)
                wmma::load_matrix_sync(a[i], ah + (wm * 64 + i * 16) * LDH + k0, LDH);
            #pragma unroll
            for (int j = 0; j < 3; j++)
                wmma::load_matrix_sync(b[j], Bs + (wn * 48 + j * 16) * LDH + k0, LDH);
            #pragma unroll
            for (int i = 0; i < 4; i++)
                #pragma unroll
                for (int j = 0; j < 3; j++)
                    wmma::mma_sync(c[i][j], a[i], b[j], c[i][j]);
        }

        // prefetch chunk kc+2:
        //   A -> abuf[kc&1]        (own pieces; converted at iter kc-1)
        //   B -> bbuf[(kc+2)%3]    (== (kc-1)%3; readers passed this barrier)
        if (kc + 2 < NCH) issue_stage(kc + 2, kc & 1, (kc + 2) % 3);
        CP_COMMIT();            // uniform group count even when empty

        // group for chunk kc+1 (committed last iteration) complete
        CP_WAIT(1);

        // convert NEXT chunk's A (own pieces) while HMMAs drain
        if (kc + 1 < NCH)
            convert_a((kc + 1) & 1, (kc & 1) ? ah0 : ah1);
    }
    __syncthreads();            // all warps done with stage smem

    // ---- epilogue: full 128x292 C in smem (one pass) ----
    float* Cs = reinterpret_cast<float*>(smem + SM_C);
    #pragma unroll
    for (int i = 0; i < 4; i++)
        #pragma unroll
        for (int j = 0; j < 3; j++)
            wmma::store_matrix_sync(
                Cs + (wm * 64 + i * 16) * LDC + wn * 48 + j * 16,
                c[i][j], LDC, wmma::mem_row_major);
    __syncthreads();

    // logits: float4 LDS (aligned) -> 4 scalar STG (gmem base may be 4B-aligned)
    for (int idx = tid; idx < BM * (NTOT / 4); idx += THREADS) {
        int r = idx / (NTOT / 4), n4 = idx - r * (NTOT / 4);
        float4 v  = *reinterpret_cast<const float4*>(Cs + r * LDC + n4 * 4);
        float4 bb = *reinterpret_cast<const float4*>(sbias + n4 * 4);
        float* dst = logits + (size_t)(m0 + r) * NTOT + n4 * 4;
        dst[0] = v.x + bb.x;
        dst[1] = v.y + bb.y;
        dst[2] = v.z + bb.z;
        dst[3] = v.w + bb.w;
    }

    // loss: 128 rows x 28 heads
    const int lab64 = g_lab64;
    float loss_part = 0.f;
    for (int t = tid; t < BM * 28; t += THREADS) {
        int r = t / 28, h = t - r * 28;
        const float* x  = Cs + r * LDC + h * 10;
        const float* bb = sbias + h * 10;
        float v[10], mx = -1e30f;
        #pragma unroll
        for (int i = 0; i < 10; i++) { v[i] = x[i] + bb[i]; mx = fmaxf(mx, v[i]); }
        float s = 0.f;
        #pragma unroll
        for (int i = 0; i < 10; i++) s += __expf(v[i] - mx);
        int li = (m0 + r) * 28 + h;
        int label = lab64 ? lab[2 * li] : lab[li];
        loss_part += mx + __logf(s) - v[label];
    }

    #pragma unroll
    for (int off = 16; off > 0; off >>= 1)
        loss_part += __shfl_xor_sync(0xFFFFFFFF, loss_part, off);
    __shared__ float warp_loss[12];
    if ((tid & 31) == 0) warp_loss[wid] = loss_part;
    __syncthreads();
    if (tid == 0) {
        float t = 0.f;
        #pragma unroll
        for (int i = 0; i < 12; i++) t += warp_loss[i];
        atomicAdd(loss_out, t * (1.0f / ((float)batch * 28.0f)));
    }
}

// ============================================================================
// kernel_launch
// ============================================================================
extern "C" void kernel_launch(void* const* d_in, const int* in_sizes, int n_in,
                              void* d_out, int out_size)
{
    const float* hidden = (const float*)d_in[0];
    const int*   labels = (const int*)d_in[1];
    const float* W      = (const float*)d_in[2];
    const float* bias   = (const float*)d_in[3];

    const int batch = in_sizes[0] / KDIM;                  // 32768
    const long long LOGN = (long long)batch * NTOT;

    float* out = (float*)d_out;
    float* loss_ptr = nullptr;
    float* logits_ptr = nullptr;
    if ((long long)out_size >= LOGN + 1) {
        loss_ptr = out;
        logits_ptr = out + 1;
    } else if ((long long)out_size == LOGN) {
        logits_ptr = out;
    } else {
        loss_ptr = out;
    }
    if (!loss_ptr) {
        void* p = nullptr;
        cudaGetSymbolAddress(&p, g_loss_scratch);
        loss_ptr = (float*)p;
    }

    static bool attr_done = false;
    if (!attr_done) {
        cudaFuncSetAttribute(gemm_loss_kernel,
                             cudaFuncAttributeMaxDynamicSharedMemorySize, SM_TOTAL);
        attr_done = true;
    }

    prep_w_kernel<<<(NPAD * KDIM + 255) / 256, 256>>>(W, labels);
    cudaMemsetAsync(loss_ptr, 0, sizeof(float));
    gemm_loss_kernel<<<batch / BM, THREADS, SM_TOTAL>>>(
        hidden, bias, labels, logits_ptr, loss_ptr, batch);
}

// round 17
// speedup vs baseline: 2.8092x; 2.8092x over previous
#include <cuda_runtime.h>
#include <cuda_fp16.h>
#include <mma.h>
#include <cstdint>
#include <cstddef>

using namespace nvcuda;

// ============================================================================
// Problem: hidden [B,2048] f32, labels [B,28] i64/i32, W [280,2048] f32,
// bias [280] f32.  logits = hidden @ W^T + bias;  loss = mean NLL / 28.
// fp16 HMMA lane, BK=64 (32 chunks). Split-depth rings: A-raw ring of 2
// (consumed by same-thread convert), B fp16 ring of 3 (barrier-protected).
// ALL smem row strides are 16 mod 128 bytes (272B raw A, 144B fp16) ->
// conflict-free LDSM / LDS / STS (R16's 256B/128B strides were 8-way
// conflicted and cost 2.7x). One __syncthreads per chunk.
// ============================================================================
static constexpr int KDIM = 2048;
static constexpr int BATCH_MAX = 32768;
static constexpr int NTOT = 280;
static constexpr int NPAD = 288;        // 18 * 16
static constexpr int BM   = 128;
static constexpr int BK   = 64;         // K per chunk
static constexpr int NCH  = KDIM / BK;  // 32
static constexpr int THREADS = 384;     // 12 warps: 2 (m) x 6 (n)

static constexpr int LDH     = 72;      // fp16 row stride in halves (144B)
static constexpr int A_RAW_LD= 272;     // raw A row stride in bytes (68 f32)
static constexpr int LDC     = 292;     // f32 C rows

// SMEM layout (bytes)
static constexpr int SM_BIAS = 0;                         // 288 f32 (1152B)
static constexpr int SM_A    = 1280;                      // A raw ring x2
static constexpr int A_SZ    = BM * A_RAW_LD;             // 34816
static constexpr int SM_B    = SM_A + 2 * A_SZ;           // 70912, B ring x3
static constexpr int B_SZ    = NPAD * LDH * 2;            // 41472
static constexpr int SM_AH   = SM_B + 3 * B_SZ;           // 195328, ah x2
static constexpr int AH_SZ   = BM * LDH * 2;              // 18432
static constexpr int SM_END  = SM_AH + 2 * AH_SZ;         // 232192
static constexpr int SM_C    = SM_A;                      // epilogue reuse
static constexpr int SM_EPI  = SM_A + BM * LDC * 4;       // 150784
static constexpr int SM_TOTAL = (SM_END > SM_EPI) ? SM_END : SM_EPI;  // 232192

__device__ __forceinline__ uint32_t smem_u32(const void* p) {
    uint32_t a;
    asm("{ .reg .u64 t; cvta.to.shared.u64 t, %1; cvt.u32.u64 %0, t; }"
        : "=r"(a) : "l"(p));
    return a;
}

#define CP_ASYNC16(dst, src) \
    asm volatile("cp.async.cg.shared.global [%0], [%1], 16;" \
                 :: "r"(dst), "l"(src))
#define CP_COMMIT() asm volatile("cp.async.commit_group;" ::: "memory")
#define CP_WAIT(n)  asm volatile("cp.async.wait_group %0;" :: "n"(n) : "memory")

// ============================================================================
// Device scratch
// ============================================================================
__device__ __align__(16) __half g_whalf[NPAD * KDIM];   // fp16 W, zero-padded
__device__ float  g_logits_scratch[(size_t)BATCH_MAX * NTOT];
__device__ float  g_loss_scratch[1];
__device__ int    g_lab64;

// ============================================================================
// Prep: W -> g_whalf (fp16 RN, rows >= 280 zero). Label dtype detect.
// ============================================================================
__global__ void prep_w_kernel(const float* __restrict__ W,
                              const int* __restrict__ lab) {
    int idx = blockIdx.x * blockDim.x + threadIdx.x;
    if (idx < NPAD * KDIM) {
        int r = idx >> 11;   // / 2048
        g_whalf[idx] = (r < NTOT) ? __float2half_rn(W[idx]) : __half(0.f);
    }
    if (idx == 0) {
        int odd_or = 0;
        #pragma unroll 8
        for (int i = 0; i < 64; i++) odd_or |= lab[2 * i + 1];
        g_lab64 = (odd_or == 0) ? 1 : 0;
    }
}

// ============================================================================
// Fused GEMM (fp16 wmma m16n16k16, BK=64) + bias + logits + loss
// Loop: sync -> MMA(kc) -> issue(kc+2) -> commit -> wait(1) -> convert(kc+1).
// ============================================================================
__global__ void __launch_bounds__(THREADS, 1)
gemm_loss_kernel(const float* __restrict__ hidden,
                 const float* __restrict__ bias,
                 const int*   __restrict__ lab,
                 float* __restrict__ logits_arg,
                 float* __restrict__ loss_out,
                 int batch)
{
    extern __shared__ char smem[];
    float* sbias = reinterpret_cast<float*>(smem + SM_BIAS);
    float* logits = logits_arg ? logits_arg : g_logits_scratch;

    const uint32_t sbase = smem_u32(smem);
    const int tid = threadIdx.x;
    const int wid = tid >> 5;
    const int wm  = wid / 6;     // 0..1 -> 64-row slice
    const int wn  = wid % 6;     // 0..5 -> 48-col slice
    const int m0  = blockIdx.x * BM;

    for (int i = tid; i < NPAD; i += THREADS)
        sbias[i] = (i < NTOT) ? bias[i] : 0.f;

    wmma::fragment<wmma::accumulator, 16, 16, 16, float> c[4][3];
    #pragma unroll
    for (int i = 0; i < 4; i++)
        #pragma unroll
        for (int j = 0; j < 3; j++)
            wmma::fill_fragment(c[i][j], 0.f);

    // ---- cp.async: A raw f32 128x64 (2048 x 16B), B fp16 288x64 (2304 x 16B)
    auto issue_stage = [&](int kc2, int ab, int bb) {
        const uint32_t a_dst = sbase + SM_A + ab * A_SZ;
        const uint32_t b_dst = sbase + SM_B + bb * B_SZ;
        const int k0 = kc2 * BK;
        #pragma unroll
        for (int i = 0; i < 6; i++) {
            int idx = tid + i * THREADS;
            if (idx < 2048) {
                int r = idx >> 4, v = idx & 15;
                const float* src = hidden + (size_t)(m0 + r) * KDIM + k0 + v * 4;
                CP_ASYNC16(a_dst + (uint32_t)(r * A_RAW_LD + v * 16), src);
            }
        }
        #pragma unroll
        for (int i = 0; i < 6; i++) {
            int idx = tid + i * THREADS;
            int r = idx >> 3, v = idx & 7;
            const __half* src = g_whalf + (size_t)r * KDIM + k0 + v * 8;
            CP_ASYNC16(b_dst + (uint32_t)(r * 144 + v * 16), src);
        }
    };

    // Convert THIS thread's own A pieces of abuf `ab` -> fp16 dst_ah.
    // Own cp.async data is visible after wait_group (no barrier needed).
    auto convert_a = [&](int ab, __half* dst_ah) {
        const char* stg = smem + SM_A + ab * A_SZ;
        #pragma unroll
        for (int i = 0; i < 6; i++) {
            int idx = tid + i * THREADS;
            if (idx < 2048) {
                int r = idx >> 4, v = idx & 15;
                float4 f = *reinterpret_cast<const float4*>(
                    stg + r * A_RAW_LD + v * 16);
                __half2 h0 = __floats2half2_rn(f.x, f.y);
                __half2 h1 = __floats2half2_rn(f.z, f.w);
                uint2 u = make_uint2(*reinterpret_cast<uint32_t*>(&h0),
                                     *reinterpret_cast<uint32_t*>(&h1));
                *reinterpret_cast<uint2*>(dst_ah + r * LDH + v * 4) = u;
            }
        }
    };

    __half* ah0 = reinterpret_cast<__half*>(smem + SM_AH);
    __half* ah1 = reinterpret_cast<__half*>(smem + SM_AH + AH_SZ);

    // prologue: chunks 0,1 in flight; convert chunk 0 (own pieces)
    issue_stage(0, 0, 0); CP_COMMIT();
    issue_stage(1, 1, 1); CP_COMMIT();
    CP_WAIT(1);                 // own chunk-0 copies complete
    convert_a(0, ah0);

    for (int kc = 0; kc < NCH; kc++) {
        __syncthreads();        // publishes bbuf[kc%3] (all threads' B copies)
                                // and ah[kc&1]; frees bbuf[(kc-1)%3] + ah other

        // MMA chunk kc: A from ah[kc&1], B from bbuf[kc%3]
        const __half* ah = (kc & 1) ? ah1 : ah0;
        const __half* Bs = reinterpret_cast<const __half*>(
            smem + SM_B + (kc % 3) * B_SZ);

        #pragma unroll
        for (int ks = 0; ks < 4; ks++) {
            const int k0 = ks * 16;
            wmma::fragment<wmma::matrix_a, 16, 16, 16, __half,
                           wmma::row_major> a[4];
            wmma::fragment<wmma::matrix_b, 16, 16, 16, __half,
                           wmma::col_major> b[3];
            #pragma unroll
            for (int i = 0; i < 4; i++)
                wmma::load_matrix_sync(a[i], ah + (wm * 64 + i * 16) * LDH + k0, LDH);
            #pragma unroll
            for (int j = 0; j < 3; j++)
                wmma::load_matrix_sync(b[j], Bs + (wn * 48 + j * 16) * LDH + k0, LDH);
            #pragma unroll
            for (int i = 0; i < 4; i++)
                #pragma unroll
                for (int j = 0; j < 3; j++)
                    wmma::mma_sync(c[i][j], a[i], b[j], c[i][j]);
        }

        // prefetch chunk kc+2:
        //   A -> abuf[kc&1]        (own pieces; converted at iter kc-1)
        //   B -> bbuf[(kc+2)%3]    (== (kc-1)%3; readers passed this barrier)
        if (kc + 2 < NCH) issue_stage(kc + 2, kc & 1, (kc + 2) % 3);
        CP_COMMIT();            // uniform group count even when empty

        // group for chunk kc+1 (committed last iteration) complete
        CP_WAIT(1);

        // convert NEXT chunk's A (own pieces) while HMMAs drain
        if (kc + 1 < NCH)
            convert_a((kc + 1) & 1, (kc & 1) ? ah0 : ah1);
    }
    __syncthreads();            // all warps done with stage smem

    // ---- epilogue: full 128x292 C in smem (one pass) ----
    float* Cs = reinterpret_cast<float*>(smem + SM_C);
    #pragma unroll
    for (int i = 0; i < 4; i++)
        #pragma unroll
        for (int j = 0; j < 3; j++)
            wmma::store_matrix_sync(
                Cs + (wm * 64 + i * 16) * LDC + wn * 48 + j * 16,
                c[i][j], LDC, wmma::mem_row_major);
    __syncthreads();

    // logits: float4 LDS (aligned) -> 4 scalar STG (gmem base may be 4B-aligned)
    for (int idx = tid; idx < BM * (NTOT / 4); idx += THREADS) {
        int r = idx / (NTOT / 4), n4 = idx - r * (NTOT / 4);
        float4 v  = *reinterpret_cast<const float4*>(Cs + r * LDC + n4 * 4);
        float4 bb = *reinterpret_cast<const float4*>(sbias + n4 * 4);
        float* dst = logits + (size_t)(m0 + r) * NTOT + n4 * 4;
        dst[0] = v.x + bb.x;
        dst[1] = v.y + bb.y;
        dst[2] = v.z + bb.z;
        dst[3] = v.w + bb.w;
    }

    // loss: 128 rows x 28 heads
    const int lab64 = g_lab64;
    float loss_part = 0.f;
    for (int t = tid; t < BM * 28; t += THREADS) {
        int r = t / 28, h = t - r * 28;
        const float* x  = Cs + r * LDC + h * 10;
        const float* bb = sbias + h * 10;
        float v[10], mx = -1e30f;
        #pragma unroll
        for (int i = 0; i < 10; i++) { v[i] = x[i] + bb[i]; mx = fmaxf(mx, v[i]); }
        float s = 0.f;
        #pragma unroll
        for (int i = 0; i < 10; i++) s += __expf(v[i] - mx);
        int li = (m0 + r) * 28 + h;
        int label = lab64 ? lab[2 * li] : lab[li];
        loss_part += mx + __logf(s) - v[label];
    }

    #pragma unroll
    for (int off = 16; off > 0; off >>= 1)
        loss_part += __shfl_xor_sync(0xFFFFFFFF, loss_part, off);
    __shared__ float warp_loss[12];
    if ((tid & 31) == 0) warp_loss[wid] = loss_part;
    __syncthreads();
    if (tid == 0) {
        float t = 0.f;
        #pragma unroll
        for (int i = 0; i < 12; i++) t += warp_loss[i];
        atomicAdd(loss_out, t * (1.0f / ((float)batch * 28.0f)));
    }
}

// ============================================================================
// kernel_launch
// ============================================================================
extern "C" void kernel_launch(void* const* d_in, const int* in_sizes, int n_in,
                              void* d_out, int out_size)
{
    const float* hidden = (const float*)d_in[0];
    const int*   labels = (const int*)d_in[1];
    const float* W      = (const float*)d_in[2];
    const float* bias   = (const float*)d_in[3];

    const int batch = in_sizes[0] / KDIM;                  // 32768
    const long long LOGN = (long long)batch * NTOT;

    float* out = (float*)d_out;
    float* loss_ptr = nullptr;
    float* logits_ptr = nullptr;
    if ((long long)out_size >= LOGN + 1) {
        loss_ptr = out;
        logits_ptr = out + 1;
    } else if ((long long)out_size == LOGN) {
        logits_ptr = out;
    } else {
        loss_ptr = out;
    }
    if (!loss_ptr) {
        void* p = nullptr;
        cudaGetSymbolAddress(&p, g_loss_scratch);
        loss_ptr = (float*)p;
    }

    static bool attr_done = false;
    if (!attr_done) {
        cudaFuncSetAttribute(gemm_loss_kernel,
                             cudaFuncAttributeMaxDynamicSharedMemorySize, SM_TOTAL);
        attr_done = true;
    }

    prep_w_kernel<<<(NPAD * KDIM + 255) / 256, 256>>>(W, labels);
    cudaMemsetAsync(loss_ptr, 0, sizeof(float));
    gemm_loss_kernel<<<batch / BM, THREADS, SM_TOTAL>>>(
        hidden, bias, labels, logits_ptr, loss_ptr, batch);
}